// round 15
// baseline (speedup 1.0000x reference)
#include <cuda_runtime.h>
#include <cuda_bf16.h>
#include <math.h>
#include <float.h>
#include <stdint.h>

// ---------------------------------------------------------------------------
// MatchLSTM: B=128, P=K=64, E=H=300, V=50000, C=3
//  GEMMs: bf16 mma.sync.m16n8k16 + ldmatrix, double-buffered SMEM, fused bias.
//  Scan: 512 thr/block; WmT in SMEM; hsWa in regs; tproj/htpre prefetch;
//  all-warp softmax; Phase-B 4-row ILP; Phase-C plen early-exit.
// ---------------------------------------------------------------------------

// offsets in f32 units
constexpr size_t OFF_GATES1 = 0;                        // 8192*900 bf16
constexpr size_t OFF_GATES2 = OFF_GATES1 + 3686400;     // 8192*900 bf16
constexpr size_t OFF_HS     = OFF_GATES2 + 3686400;     // 8192*300 bf16
constexpr size_t OFF_HT     = OFF_HS     + 1228800;
constexpr size_t OFF_SPROJ  = OFF_HT     + 1228800;     // 8192*300 bf16
constexpr size_t OFF_TPROJ  = OFF_SPROJ  + 1228800;     // 8192*300 bf16
constexpr size_t OFF_HTPRE  = OFF_TPROJ  + 1228800;     // 8192*900 bf16 (+biasM)
constexpr size_t OFF_HSWA   = OFF_HTPRE  + 3686400;     // 8192*900 bf16
constexpr size_t OFF_WPB    = OFF_HSWA   + 3686400;     // 900*300 bf16
constexpr size_t OFF_WHB    = OFF_WPB    + 135000;
constexpr size_t OFF_WAB    = OFF_WHB    + 135000;
constexpr size_t OFF_WHMB   = OFF_WAB    + 135000;
constexpr size_t OFF_WSB    = OFF_WHMB   + 135000;      // 300*300 bf16
constexpr size_t OFF_WTB    = OFF_WSB    + 45000;
constexpr size_t OFF_WMTB   = OFF_WTB    + 45000;       // 300*300 bf16
constexpr size_t OFF_BP     = OFF_WMTB   + 45000;       // 900 f32
constexpr size_t OFF_BH     = OFF_BP + 900;
constexpr size_t OFF_BM     = OFF_BH + 900;
constexpr size_t BUF_TOTAL  = OFF_BM + 900;

__device__ __align__(16) float g_buf[BUF_TOTAL];

__device__ __forceinline__ float tanh_apx(float x) {
    float y; asm("tanh.approx.f32 %0, %1;" : "=f"(y) : "f"(x)); return y;
}
__device__ __forceinline__ float sig_apx(float x) {
    return fmaf(0.5f, tanh_apx(0.5f * x), 0.5f);
}

__device__ __forceinline__ uint32_t smem_u32(const void* p) {
    uint32_t a;
    asm("{ .reg .u64 t; cvta.to.shared.u64 t, %1; cvt.u32.u64 %0, t; }" : "=r"(a) : "l"(p));
    return a;
}
__device__ __forceinline__ void ldsm_x4(uint32_t r[4], uint32_t addr) {
    asm volatile("ldmatrix.sync.aligned.m8n8.x4.shared.b16 {%0,%1,%2,%3}, [%4];"
                 : "=r"(r[0]), "=r"(r[1]), "=r"(r[2]), "=r"(r[3]) : "r"(addr));
}
__device__ __forceinline__ void mma_bf16(float c[4], const uint32_t a[4],
                                         uint32_t b0, uint32_t b1) {
    asm volatile(
        "mma.sync.aligned.m16n8k16.row.col.f32.bf16.bf16.f32 "
        "{%0,%1,%2,%3}, {%4,%5,%6,%7}, {%8,%9}, {%0,%1,%2,%3};"
        : "+f"(c[0]), "+f"(c[1]), "+f"(c[2]), "+f"(c[3])
        : "r"(a[0]), "r"(a[1]), "r"(a[2]), "r"(a[3]), "r"(b0), "r"(b1));
}
__device__ __forceinline__ float2 bf2f2(uint32_t u) {
    __nv_bfloat162 h = *reinterpret_cast<__nv_bfloat162*>(&u);
    return __bfloat1622float2(h);
}
__device__ __forceinline__ uint32_t tanh_bf16x2(uint32_t x) {
    uint32_t d;
    asm("tanh.approx.bf16x2 %0, %1;" : "=r"(d) : "r"(x));
    return d;
}

// ======================= fused prep (1 launch) ==============================
__global__ void prep_all(const float* __restrict__ Wih_p, const float* __restrict__ bih_p,
                         const float* __restrict__ bhh_p,
                         const float* __restrict__ Wih_h, const float* __restrict__ bih_h,
                         const float* __restrict__ bhh_h,
                         const float* __restrict__ Wih_m, const float* __restrict__ bih_m,
                         const float* __restrict__ bhh_m,
                         const float* __restrict__ Wm,
                         const float* __restrict__ Ws, const float* __restrict__ Wt,
                         __nv_bfloat16* __restrict__ Wp, __nv_bfloat16* __restrict__ Wh,
                         __nv_bfloat16* __restrict__ Wa, __nv_bfloat16* __restrict__ Whm,
                         __nv_bfloat16* __restrict__ Wsb, __nv_bfloat16* __restrict__ Wtb,
                         __nv_bfloat16* __restrict__ WmT,
                         float* __restrict__ bp, float* __restrict__ bh,
                         float* __restrict__ bm)
{
    int idx = blockIdx.x * blockDim.x + threadIdx.x;
    if (idx < 270000) {
        int j = idx / 300, k2 = idx % 300;
        int src = (j < 300) ? j : j + 300;
        Wp[idx] = __float2bfloat16(Wih_p[(size_t)src * 300 + k2]);
    } else if (idx < 540000) {
        int t = idx - 270000; int j = t / 300, k2 = t % 300;
        int src = (j < 300) ? j : j + 300;
        Wh[t] = __float2bfloat16(Wih_h[(size_t)src * 300 + k2]);
    } else if (idx < 810000) {
        int t = idx - 540000; int j = t / 300, k2 = t % 300;
        int src = (j < 300) ? j : j + 300;
        Wa[t] = __float2bfloat16(Wih_m[(size_t)src * 600 + k2]);
    } else if (idx < 1080000) {
        int t = idx - 810000; int j = t / 300, k2 = t % 300;
        int src = (j < 300) ? j : j + 300;
        Whm[t] = __float2bfloat16(Wih_m[(size_t)src * 600 + 300 + k2]);
    } else if (idx < 1170000) {
        int t = idx - 1080000;
        Wsb[t] = __float2bfloat16(Ws[t]);
    } else if (idx < 1260000) {
        int t = idx - 1170000;
        Wtb[t] = __float2bfloat16(Wt[t]);
    } else if (idx < 1350000) {
        int t = idx - 1260000; int d = t / 300, j = t % 300;
        WmT[t] = __float2bfloat16(Wm[(size_t)j * 300 + d]);
    }
    if (idx < 900) {
        int src = (idx < 300) ? idx : idx + 300;
        bp[idx] = bih_p[src] + bhh_p[src];
        bh[idx] = bih_h[src] + bhh_h[src];
        bm[idx] = bih_m[src] + bhh_m[src];
    }
}

// ======================= bf16 tensor-core GEMM core =========================
constexpr int GLDK = 40;
constexpr int GBUF = 128 * GLDK;   // 5120 bf16 per buffer

template <typename AT, typename CT>
__device__ __forceinline__ void gemm_core(
    const AT* __restrict__ A, const int* __restrict__ tok,
    const __nv_bfloat16* __restrict__ B, int Brows,
    CT* __restrict__ C, int N, const float* __restrict__ bias,
    __nv_bfloat16* __restrict__ sm, int mbase, int nbase)
{
    constexpr bool AF32 = (sizeof(AT) == 4);
    const int tid = threadIdx.x;
    const int warp = tid >> 5, lane = tid & 31;
    const int wm = warp >> 2, wn = warp & 3;

    const uint32_t aB[2] = { smem_u32(sm),            smem_u32(sm + GBUF) };
    const uint32_t bB[2] = { smem_u32(sm + 2 * GBUF), smem_u32(sm + 3 * GBUF) };

    int arow_s[4], asrc[4], ac4[4];
    bool bok[4];
#pragma unroll
    for (int p = 0; p < 4; ++p) {
        const int f4 = tid + 256 * p;
        const int row = f4 >> 3;
        arow_s[p] = row;
        ac4[p]    = f4 & 7;
        const int gm = mbase + row;
        asrc[p] = tok ? tok[gm] : gm;
        bok[p]  = (nbase + row) < Brows;
    }

    float acc[4][4][4];
#pragma unroll
    for (int i = 0; i < 4; i++)
#pragma unroll
        for (int n = 0; n < 4; n++)
#pragma unroll
            for (int e = 0; e < 4; e++) acc[i][n][e] = 0.f;

    const int lrow = lane & 15;
    const int lkof = (lane >> 4) << 3;

    float4 vaf[4];
    uint2  vab[4], vbb[4];

    auto load_chunk = [&](int k0) {
#pragma unroll
        for (int p = 0; p < 4; ++p) {
            const int kk = k0 + ac4[p] * 4;
            const bool kv = (kk < 300);
            if (AF32) {
                vaf[p] = kv ? *reinterpret_cast<const float4*>((const float*)A + (size_t)asrc[p] * 300 + kk)
                            : make_float4(0.f, 0.f, 0.f, 0.f);
            } else {
                vab[p] = kv ? *reinterpret_cast<const uint2*>((const __nv_bfloat16*)A + (size_t)asrc[p] * 300 + kk)
                            : make_uint2(0u, 0u);
            }
            vbb[p] = (kv && bok[p])
                ? *reinterpret_cast<const uint2*>(B + (size_t)(nbase + arow_s[p]) * 300 + kk)
                : make_uint2(0u, 0u);
        }
    };
    auto store_chunk = [&](int buf) {
        __nv_bfloat16* Asb = sm + buf * GBUF;
        __nv_bfloat16* Bsb = sm + (2 + buf) * GBUF;
#pragma unroll
        for (int p = 0; p < 4; ++p) {
            const int off = arow_s[p] * GLDK + ac4[p] * 4;
            if (AF32) {
                __nv_bfloat162 alo = __float22bfloat162_rn(make_float2(vaf[p].x, vaf[p].y));
                __nv_bfloat162 ahi = __float22bfloat162_rn(make_float2(vaf[p].z, vaf[p].w));
                *reinterpret_cast<uint2*>(&Asb[off]) =
                    make_uint2(*reinterpret_cast<uint32_t*>(&alo), *reinterpret_cast<uint32_t*>(&ahi));
            } else {
                *reinterpret_cast<uint2*>(&Asb[off]) = vab[p];
            }
            *reinterpret_cast<uint2*>(&Bsb[off]) = vbb[p];
        }
    };

    load_chunk(0);
    store_chunk(0);
    __syncthreads();

#pragma unroll 1
    for (int c = 0; c < 10; ++c) {
        if (c < 9) load_chunk((c + 1) * 32);
        const uint32_t a0 = aB[c & 1], b0 = bB[c & 1];
#pragma unroll
        for (int j = 0; j < 2; ++j) {
            const int kcol = j * 16 + lkof;
            uint32_t af[4][4], bfr[2][4];
#pragma unroll
            for (int i = 0; i < 4; ++i)
                ldsm_x4(af[i], a0 + (uint32_t)(((wm * 64 + i * 16 + lrow) * GLDK + kcol) * 2));
#pragma unroll
            for (int nt = 0; nt < 2; ++nt)
                ldsm_x4(bfr[nt], b0 + (uint32_t)(((wn * 32 + nt * 16 + lrow) * GLDK + kcol) * 2));
#pragma unroll
            for (int i = 0; i < 4; ++i)
#pragma unroll
                for (int n = 0; n < 4; ++n) {
                    const int nt = n >> 1, s = n & 1;
                    mma_bf16(acc[i][n], af[i], bfr[nt][s], bfr[nt][s + 2]);
                }
        }
        if (c < 9) { store_chunk((c + 1) & 1); __syncthreads(); }
    }

#pragma unroll
    for (int i = 0; i < 4; ++i) {
        const int r = mbase + wm * 64 + i * 16 + (lane >> 2);
#pragma unroll
        for (int n = 0; n < 4; ++n) {
            const int col = nbase + wn * 32 + n * 8 + (lane & 3) * 2;
            if (col < N) {
                float2 bv = make_float2(0.f, 0.f);
                if (bias) bv = *reinterpret_cast<const float2*>(bias + col);
                float v0 = acc[i][n][0] + bv.x, v1 = acc[i][n][1] + bv.y;
                float v2 = acc[i][n][2] + bv.x, v3 = acc[i][n][3] + bv.y;
                if (sizeof(CT) == 4) {
                    *reinterpret_cast<float2*>((float*)C + (size_t)r * N + col) = make_float2(v0, v1);
                    *reinterpret_cast<float2*>((float*)C + (size_t)(r + 8) * N + col) = make_float2(v2, v3);
                } else {
                    __nv_bfloat162 lo = __float22bfloat162_rn(make_float2(v0, v1));
                    __nv_bfloat162 hi = __float22bfloat162_rn(make_float2(v2, v3));
                    *reinterpret_cast<uint32_t*>((__nv_bfloat16*)C + (size_t)r * N + col) =
                        *reinterpret_cast<uint32_t*>(&lo);
                    *reinterpret_cast<uint32_t*>((__nv_bfloat16*)C + (size_t)(r + 8) * N + col) =
                        *reinterpret_cast<uint32_t*>(&hi);
                }
            }
        }
    }
}

// encoders: z=0 premise, z=1 hypothesis (f32 gather A, bf16 C, fused bias)
__global__ __launch_bounds__(256, 2)
void gemm_enc(const float* __restrict__ embed,
              const int* __restrict__ tokA, const int* __restrict__ tokB,
              const __nv_bfloat16* __restrict__ WA, const __nv_bfloat16* __restrict__ WB,
              const float* __restrict__ bA, const float* __restrict__ bB2,
              __nv_bfloat16* __restrict__ CA, __nv_bfloat16* __restrict__ CB)
{
    __shared__ __nv_bfloat16 sm[4 * GBUF];
    const int z = blockIdx.z;
    gemm_core<float, __nv_bfloat16>(embed, z ? tokB : tokA, z ? WB : WA, 900,
                                    z ? CB : CA, 900, z ? bB2 : bA, sm,
                                    blockIdx.y * 128, blockIdx.x * 128);
}

// 4 precomputes in one launch (bf16 A, bf16 C)
struct Pre4 {
    const __nv_bfloat16* A[4];
    const __nv_bfloat16* B[4];
    __nv_bfloat16*       C[4];
    const float*         bias[4];
    int                  N[4];
};
__global__ __launch_bounds__(256, 2)
void gemm_pre(Pre4 a)
{
    __shared__ __nv_bfloat16 sm[4 * GBUF];
    const int z = blockIdx.z;
    const int N = a.N[z];
    const int nbase = blockIdx.x * 128;
    if (nbase >= N) return;
    gemm_core<__nv_bfloat16, __nv_bfloat16>(a.A[z], nullptr, a.B[z], N,
                                            a.C[z], N, a.bias[z], sm,
                                            blockIdx.y * 128, nbase);
}

// ======================= lstm0 activation (bf16 gates in) ===================
__global__ void lstm_act2(const __nv_bfloat16* __restrict__ G1,
                          const __nv_bfloat16* __restrict__ G2,
                          __nv_bfloat16* __restrict__ h1, __nv_bfloat16* __restrict__ h2)
{
    int idx = blockIdx.x * blockDim.x + threadIdx.x;
    if (idx >= 8192 * 150) return;
    const __nv_bfloat16* G = blockIdx.y ? G2 : G1;
    __nv_bfloat16* h = blockIdx.y ? h2 : h1;
    int m = idx / 150, j2 = (idx % 150) * 2;
    const uint32_t* g = reinterpret_cast<const uint32_t*>(G + (size_t)m * 900);
    float2 gi = bf2f2(g[j2 / 2]);
    float2 gg = bf2f2(g[(j2 + 300) / 2]);
    float2 go = bf2f2(g[(j2 + 600) / 2]);
    float c0 = sig_apx(gi.x) * tanh_apx(gg.x);
    float c1 = sig_apx(gi.y) * tanh_apx(gg.y);
    float v0 = sig_apx(go.x) * tanh_apx(c0);
    float v1 = sig_apx(go.y) * tanh_apx(c1);
    __nv_bfloat162 o2 = __float22bfloat162_rn(make_float2(v0, v1));
    *reinterpret_cast<uint32_t*>(h + (size_t)m * 300 + j2) = *reinterpret_cast<uint32_t*>(&o2);
}

// ======================= persistent per-batch scan (512 thr) ================
constexpr int SM_WMT = 0;        // 90000 bf16 = 180000
constexpr int SM_SP  = 180000;   // 19200 bf16 = 38400
constexpr int SM_SCR = 218400;   // 1800 f32 = 7200 (A partials; C gates)
constexpr int SM_WE  = 225600;   // 300 f32
constexpr int SM_HM  = 226800;   // 300 f32
constexpr int SM_AL  = 228000;   // 64 f32 (raw e)
constexpr int SM_TM  = 228256;   // 300 bf16 = 600
constexpr int SM_RED = 228856;   // 8 f32
constexpr int SM_ALN = 228896;   // 64 f32 (normalized alpha, 16B aligned)
constexpr int SCAN_SMEM_BYTES = 229152;

__global__ __launch_bounds__(512)
void scan_kernel(const __nv_bfloat16* __restrict__ sproj, const __nv_bfloat16* __restrict__ tproj,
                 const __nv_bfloat16* __restrict__ htpre, const __nv_bfloat16* __restrict__ hsWa,
                 const __nv_bfloat16* __restrict__ WmTg,  const float* __restrict__ w_e,
                 const int* __restrict__ plen_a,  const int* __restrict__ hlen_a,
                 const float* __restrict__ fcw,   const float* __restrict__ fcb,
                 float* __restrict__ out)
{
    extern __shared__ char smraw[];
    __nv_bfloat16* wmt   = reinterpret_cast<__nv_bfloat16*>(smraw + SM_WMT);
    __nv_bfloat16* sp    = reinterpret_cast<__nv_bfloat16*>(smraw + SM_SP);
    float*         scr   = reinterpret_cast<float*>(smraw + SM_SCR);
    float*         we_s  = reinterpret_cast<float*>(smraw + SM_WE);
    float*         hm    = reinterpret_cast<float*>(smraw + SM_HM);
    float*         alpha = reinterpret_cast<float*>(smraw + SM_AL);
    __nv_bfloat16* tm    = reinterpret_cast<__nv_bfloat16*>(smraw + SM_TM);
    float*         red   = reinterpret_cast<float*>(smraw + SM_RED);
    float*         alpn  = reinterpret_cast<float*>(smraw + SM_ALN);

    const int b    = blockIdx.x;
    const int tid  = threadIdx.x;
    const int warp = tid >> 5, lane = tid & 31;

    for (int i = tid; i < 11250; i += 512)
        reinterpret_cast<uint4*>(wmt)[i] = reinterpret_cast<const uint4*>(WmTg)[i];
    const uint4* spg = reinterpret_cast<const uint4*>(sproj + (size_t)b * 19200);
    for (int i = tid; i < 2400; i += 512)
        reinterpret_cast<uint4*>(sp)[i] = spg[i];
    for (int i = tid; i < 300; i += 512) { we_s[i] = w_e[i]; hm[i] = 0.f; }
    const int plen = plen_a[b];
    const int hlen = hlen_a[b];

    // hsWa is k-invariant: 64 rows in registers (column pair per thread)
    uint32_t pre[64];
    if (tid < 450) {
        const uint32_t* hwp = reinterpret_cast<const uint32_t*>(
                                  hsWa + (size_t)b * (64 * 900)) + tid;
#pragma unroll
        for (int p = 0; p < 64; ++p)
            pre[p] = hwp[(size_t)p * 450];
    }
    __syncthreads();

    // w_e pairs for Phase B are step- and row-invariant: registers
    float2 we2[5];
#pragma unroll
    for (int i = 0; i < 5; ++i) {
        const int hp = lane + 32 * i;
        we2[i] = (hp < 150) ? *reinterpret_cast<const float2*>(we_s + 2 * hp)
                            : make_float2(0.f, 0.f);
    }

    // Phase B fixed row assignment: rows warp, warp+16, warp+32, warp+48.
    // plen >= 32 guarantees rows warp and warp+16 are always valid.
    const int pB2 = warp + 32, pB3 = warp + 48;

    for (int k = 0; k < hlen; ++k) {
        // prefetch step-k streams (consumed >2K cycles later)
        uint32_t prh = 0;
        uint2 tkv = make_uint2(0u, 0u);
        if (tid < 450)
            prh = __ldcs(reinterpret_cast<const uint32_t*>(
                      htpre + ((size_t)b * 64 + k) * 900) + tid);
        if (tid < 75)
            tkv = __ldcs(reinterpret_cast<const uint2*>(
                      tproj + ((size_t)b * 64 + k) * 300) + tid);

        // Phase A: m_proj partials = hm @ Wm^T (6 segs x 75 col-quads), d-pairs
        if (k > 0 && tid < 450) {
            const int seg = tid / 75;
            const int jq  = tid % 75;
            const int d0  = seg * 50;
            float4 acc = make_float4(0.f, 0.f, 0.f, 0.f);
#pragma unroll 5
            for (int d = d0; d < d0 + 50; d += 2) {
                const float2 hv = *reinterpret_cast<const float2*>(hm + d);
                const uint2 w0 = *reinterpret_cast<const uint2*>(wmt + d * 300 + jq * 4);
                const uint2 w1 = *reinterpret_cast<const uint2*>(wmt + (d + 1) * 300 + jq * 4);
                float2 a0 = bf2f2(w0.x), a1 = bf2f2(w0.y);
                float2 b0 = bf2f2(w1.x), b1 = bf2f2(w1.y);
                acc.x = fmaf(hv.x, a0.x, fmaf(hv.y, b0.x, acc.x));
                acc.y = fmaf(hv.x, a0.y, fmaf(hv.y, b0.y, acc.y));
                acc.z = fmaf(hv.x, a1.x, fmaf(hv.y, b1.x, acc.z));
                acc.w = fmaf(hv.x, a1.y, fmaf(hv.y, b1.y, acc.w));
            }
            reinterpret_cast<float4*>(scr)[seg * 75 + jq] = acc;
        }
        __syncthreads();

        // reduce partials -> mp; tm = bf16(tk + mp); tk already in regs
        if (tid < 75) {
            float4 m = make_float4(0.f, 0.f, 0.f, 0.f);
            if (k > 0) {
#pragma unroll
                for (int s = 0; s < 6; ++s) {
                    float4 a = reinterpret_cast<float4*>(scr)[s * 75 + tid];
                    m.x += a.x; m.y += a.y; m.z += a.z; m.w += a.w;
                }
            }
            float2 t0 = bf2f2(tkv.x), t1 = bf2f2(tkv.y);
            __nv_bfloat162 p0 = __float22bfloat162_rn(make_float2(m.x + t0.x, m.y + t0.y));
            __nv_bfloat162 p1 = __float22bfloat162_rn(make_float2(m.z + t1.x, m.w + t1.y));
            *reinterpret_cast<uint2*>(tm + 4 * tid) =
                make_uint2(*reinterpret_cast<uint32_t*>(&p0), *reinterpret_cast<uint32_t*>(&p1));
        }
        __syncthreads();

        // Phase B: e[p] = w_e . tanh(sp[p] + tm); single pass, 4-row ILP
        {
            const uint32_t* tmu = reinterpret_cast<const uint32_t*>(tm);
            const uint32_t* s0 = reinterpret_cast<const uint32_t*>(sp + warp * 300);
            const uint32_t* s1 = reinterpret_cast<const uint32_t*>(sp + (warp + 16) * 300);
            const uint32_t* s2 = reinterpret_cast<const uint32_t*>(sp + pB2 * 300);
            const uint32_t* s3 = reinterpret_cast<const uint32_t*>(sp + pB3 * 300);
            const bool g2 = pB2 < plen, g3 = pB3 < plen;
            float a0 = 0.f, a1 = 0.f, a2 = 0.f, a3 = 0.f;
#pragma unroll
            for (int i = 0; i < 5; ++i) {
                const int hp = lane + 32 * i;
                if (hp < 150) {
                    uint32_t t2 = tmu[hp];
                    __nv_bfloat162 tmh = *reinterpret_cast<__nv_bfloat162*>(&t2);
                    {
                        uint32_t sv = s0[hp];
                        __nv_bfloat162 x2 = __hadd2(*reinterpret_cast<__nv_bfloat162*>(&sv), tmh);
                        float2 tf = bf2f2(tanh_bf16x2(*reinterpret_cast<uint32_t*>(&x2)));
                        a0 = fmaf(we2[i].x, tf.x, a0); a0 = fmaf(we2[i].y, tf.y, a0);
                    }
                    {
                        uint32_t sv = s1[hp];
                        __nv_bfloat162 x2 = __hadd2(*reinterpret_cast<__nv_bfloat162*>(&sv), tmh);
                        float2 tf = bf2f2(tanh_bf16x2(*reinterpret_cast<uint32_t*>(&x2)));
                        a1 = fmaf(we2[i].x, tf.x, a1); a1 = fmaf(we2[i].y, tf.y, a1);
                    }
                    if (g2) {
                        uint32_t sv = s2[hp];
                        __nv_bfloat162 x2 = __hadd2(*reinterpret_cast<__nv_bfloat162*>(&sv), tmh);
                        float2 tf = bf2f2(tanh_bf16x2(*reinterpret_cast<uint32_t*>(&x2)));
                        a2 = fmaf(we2[i].x, tf.x, a2); a2 = fmaf(we2[i].y, tf.y, a2);
                    }
                    if (g3) {
                        uint32_t sv = s3[hp];
                        __nv_bfloat162 x2 = __hadd2(*reinterpret_cast<__nv_bfloat162*>(&sv), tmh);
                        float2 tf = bf2f2(tanh_bf16x2(*reinterpret_cast<uint32_t*>(&x2)));
                        a3 = fmaf(we2[i].x, tf.x, a3); a3 = fmaf(we2[i].y, tf.y, a3);
                    }
                }
            }
#pragma unroll
            for (int o = 16; o > 0; o >>= 1) {
                a0 += __shfl_xor_sync(0xffffffffu, a0, o);
                a1 += __shfl_xor_sync(0xffffffffu, a1, o);
                a2 += __shfl_xor_sync(0xffffffffu, a2, o);
                a3 += __shfl_xor_sync(0xffffffffu, a3, o);
            }
            if (lane == 0) {
                alpha[warp]      = a0;
                alpha[warp + 16] = a1;
                if (g2) alpha[pB2] = a2;
                if (g3) alpha[pB3] = a3;
            }
        }
        __syncthreads();

        // softmax: ALL warps compute redundantly (identical ops, benign races),
        // each warp writes all 64 alpn entries -> no block barrier before C.
        {
            float e0 = (lane < plen) ? alpha[lane] : -FLT_MAX;
            float e1 = (lane + 32 < plen) ? alpha[lane + 32] : -FLT_MAX;
            float mx = fmaxf(e0, e1);
#pragma unroll
            for (int o = 16; o > 0; o >>= 1) mx = fmaxf(mx, __shfl_xor_sync(0xffffffffu, mx, o));
            float x0 = (lane < plen) ? __expf(e0 - mx) : 0.f;
            float x1 = (lane + 32 < plen) ? __expf(e1 - mx) : 0.f;
            float s = x0 + x1;
#pragma unroll
            for (int o = 16; o > 0; o >>= 1) s += __shfl_xor_sync(0xffffffffu, s, o);
            float inv = 1.f / s;
            alpn[lane]      = x0 * inv;
            alpn[lane + 32] = x1 * inv;
            __syncwarp();
        }

        // Phase C: gates = sum_p alpn[p]*pre[p] + htpre(+biasM); dual accs;
        // uniform early exit at plen (alpn is exactly 0 beyond plen anyway)
        if (tid < 450) {
            float2 acc0 = bf2f2(prh);
            float2 acc1 = make_float2(0.f, 0.f);
            const float4* al4 = reinterpret_cast<const float4*>(alpn);
#pragma unroll
            for (int q = 0; q < 16; ++q) {
                if (4 * q >= plen) break;
                const float4 av = al4[q];
                float2 w;
                w = bf2f2(pre[4 * q + 0]);
                acc0.x = fmaf(av.x, w.x, acc0.x); acc0.y = fmaf(av.x, w.y, acc0.y);
                w = bf2f2(pre[4 * q + 1]);
                acc1.x = fmaf(av.y, w.x, acc1.x); acc1.y = fmaf(av.y, w.y, acc1.y);
                w = bf2f2(pre[4 * q + 2]);
                acc0.x = fmaf(av.z, w.x, acc0.x); acc0.y = fmaf(av.z, w.y, acc0.y);
                w = bf2f2(pre[4 * q + 3]);
                acc1.x = fmaf(av.w, w.x, acc1.x); acc1.y = fmaf(av.w, w.y, acc1.y);
            }
            scr[2 * tid]     = acc0.x + acc1.x;
            scr[2 * tid + 1] = acc0.y + acc1.y;
        }
        __syncthreads();

        // Phase D: h_m update (MUFU approx)
        if (tid < 300) {
            float gi = scr[tid];
            float gg = scr[tid + 300];
            float go = scr[tid + 600];
            float c  = sig_apx(gi) * tanh_apx(gg);
            hm[tid]  = sig_apx(go) * tanh_apx(c);
        }
        __syncthreads();
    }

    // after the loop hm == h_m[hlen-1]
    if (warp < 3) {
        float acc = 0.f;
        for (int h = lane; h < 300; h += 32) acc += hm[h] * fcw[warp * 300 + h];
#pragma unroll
        for (int o = 16; o > 0; o >>= 1) acc += __shfl_xor_sync(0xffffffffu, acc, o);
        if (lane == 0) red[warp] = acc + fcb[warp];
    }
    __syncthreads();
    if (tid == 0) {
        float l0 = red[0], l1 = red[1], l2 = red[2];
        float mx = fmaxf(l0, fmaxf(l1, l2));
        float e0 = expf(l0 - mx), e1 = expf(l1 - mx), e2 = expf(l2 - mx);
        float inv = 1.f / (e0 + e1 + e2);
        out[b * 3 + 0] = e0 * inv;
        out[b * 3 + 1] = e1 * inv;
        out[b * 3 + 2] = e2 * inv;
    }
}

// ---------------------------------------------------------------------------
extern "C" void kernel_launch(void* const* d_in, const int* in_sizes, int n_in,
                              void* d_out, int out_size)
{
    const int*   premise = (const int*)  d_in[0];
    const int*   plen    = (const int*)  d_in[1];
    const int*   hyp     = (const int*)  d_in[2];
    const int*   hlen    = (const int*)  d_in[3];
    const float* embed   = (const float*)d_in[4];
    const float* w_e     = (const float*)d_in[5];
    const float* W_s     = (const float*)d_in[6];
    const float* W_t     = (const float*)d_in[7];
    const float* W_m     = (const float*)d_in[8];
    const float* fc_w    = (const float*)d_in[9];
    const float* fc_b    = (const float*)d_in[10];
    const float* Wih_p   = (const float*)d_in[11];
    const float* bih_p   = (const float*)d_in[13];
    const float* bhh_p   = (const float*)d_in[14];
    const float* Wih_h   = (const float*)d_in[15];
    const float* bih_h   = (const float*)d_in[17];
    const float* bhh_h   = (const float*)d_in[18];
    const float* Wih_m   = (const float*)d_in[19];
    const float* bih_m   = (const float*)d_in[21];
    const float* bhh_m   = (const float*)d_in[22];

    float* buf = nullptr;
    cudaGetSymbolAddress((void**)&buf, g_buf);
    __nv_bfloat16*  gates1 = (__nv_bfloat16*)(buf + OFF_GATES1);
    __nv_bfloat16*  gates2 = (__nv_bfloat16*)(buf + OFF_GATES2);
    __nv_bfloat16*  hs     = (__nv_bfloat16*)(buf + OFF_HS);
    __nv_bfloat16*  ht     = (__nv_bfloat16*)(buf + OFF_HT);
    __nv_bfloat16*  sprojp = (__nv_bfloat16*)(buf + OFF_SPROJ);
    __nv_bfloat16*  tprojp = (__nv_bfloat16*)(buf + OFF_TPROJ);
    __nv_bfloat16*  htprep = (__nv_bfloat16*)(buf + OFF_HTPRE);
    __nv_bfloat16*  hsWap  = (__nv_bfloat16*)(buf + OFF_HSWA);
    __nv_bfloat16*  Wp     = (__nv_bfloat16*)(buf + OFF_WPB);
    __nv_bfloat16*  Wh     = (__nv_bfloat16*)(buf + OFF_WHB);
    __nv_bfloat16*  Wa     = (__nv_bfloat16*)(buf + OFF_WAB);
    __nv_bfloat16*  Whm    = (__nv_bfloat16*)(buf + OFF_WHMB);
    __nv_bfloat16*  Wsb    = (__nv_bfloat16*)(buf + OFF_WSB);
    __nv_bfloat16*  Wtb    = (__nv_bfloat16*)(buf + OFF_WTB);
    __nv_bfloat16*  WmT    = (__nv_bfloat16*)(buf + OFF_WMTB);
    float* bp = buf + OFF_BP;
    float* bh = buf + OFF_BH;
    float* bm = buf + OFF_BM;

    prep_all<<<(1350000 + 255) / 256, 256>>>(Wih_p, bih_p, bhh_p,
                                             Wih_h, bih_h, bhh_h,
                                             Wih_m, bih_m, bhh_m,
                                             W_m, W_s, W_t,
                                             Wp, Wh, Wa, Whm, Wsb, Wtb, WmT,
                                             bp, bh, bm);

    gemm_enc<<<dim3(8, 64, 2), 256>>>(embed, premise, hyp, Wp, Wh, bp, bh,
                                      gates1, gates2);
    lstm_act2<<<dim3((8192 * 150 + 255) / 256, 2), 256>>>(gates1, gates2, hs, ht);

    Pre4 pa;
    pa.A[0] = hs;  pa.B[0] = Wa;  pa.C[0] = hsWap;  pa.bias[0] = nullptr; pa.N[0] = 900;
    pa.A[1] = ht;  pa.B[1] = Whm; pa.C[1] = htprep; pa.bias[1] = bm;      pa.N[1] = 900;
    pa.A[2] = hs;  pa.B[2] = Wsb; pa.C[2] = sprojp; pa.bias[2] = nullptr; pa.N[2] = 300;
    pa.A[3] = ht;  pa.B[3] = Wtb; pa.C[3] = tprojp; pa.bias[3] = nullptr; pa.N[3] = 300;
    gemm_pre<<<dim3(8, 64, 4), 256>>>(pa);

    cudaFuncSetAttribute(scan_kernel, cudaFuncAttributeMaxDynamicSharedMemorySize,
                         SCAN_SMEM_BYTES);
    scan_kernel<<<128, 512, SCAN_SMEM_BYTES>>>(sprojp, tprojp, htprep, hsWap, WmT,
                                               w_e, plen, hlen, fc_w, fc_b,
                                               (float*)d_out);
}

// round 16
// speedup vs baseline: 1.0146x; 1.0146x over previous
#include <cuda_runtime.h>
#include <cuda_bf16.h>
#include <math.h>
#include <float.h>
#include <stdint.h>

// ---------------------------------------------------------------------------
// MatchLSTM: B=128, P=K=64, E=H=300, V=50000, C=3
//  GEMMs: bf16 mma.sync.m16n8k16 + ldmatrix, double-buffered SMEM, fused bias.
//  Scan: 512 thr/block; WmT in SMEM; hsWa in regs; tproj/htpre prefetch;
//  all-warp softmax; Phase-B tm/w_e register caches; Phase-C plen early-exit.
// ---------------------------------------------------------------------------

// offsets in f32 units
constexpr size_t OFF_GATES1 = 0;                        // 8192*900 bf16
constexpr size_t OFF_GATES2 = OFF_GATES1 + 3686400;     // 8192*900 bf16
constexpr size_t OFF_HS     = OFF_GATES2 + 3686400;     // 8192*300 bf16
constexpr size_t OFF_HT     = OFF_HS     + 1228800;
constexpr size_t OFF_SPROJ  = OFF_HT     + 1228800;     // 8192*300 bf16
constexpr size_t OFF_TPROJ  = OFF_SPROJ  + 1228800;     // 8192*300 bf16
constexpr size_t OFF_HTPRE  = OFF_TPROJ  + 1228800;     // 8192*900 bf16 (+biasM)
constexpr size_t OFF_HSWA   = OFF_HTPRE  + 3686400;     // 8192*900 bf16
constexpr size_t OFF_WPB    = OFF_HSWA   + 3686400;     // 900*300 bf16
constexpr size_t OFF_WHB    = OFF_WPB    + 135000;
constexpr size_t OFF_WAB    = OFF_WHB    + 135000;
constexpr size_t OFF_WHMB   = OFF_WAB    + 135000;
constexpr size_t OFF_WSB    = OFF_WHMB   + 135000;      // 300*300 bf16
constexpr size_t OFF_WTB    = OFF_WSB    + 45000;
constexpr size_t OFF_WMTB   = OFF_WTB    + 45000;       // 300*300 bf16
constexpr size_t OFF_BP     = OFF_WMTB   + 45000;       // 900 f32
constexpr size_t OFF_BH     = OFF_BP + 900;
constexpr size_t OFF_BM     = OFF_BH + 900;
constexpr size_t BUF_TOTAL  = OFF_BM + 900;

__device__ __align__(16) float g_buf[BUF_TOTAL];

__device__ __forceinline__ float tanh_apx(float x) {
    float y; asm("tanh.approx.f32 %0, %1;" : "=f"(y) : "f"(x)); return y;
}
__device__ __forceinline__ float sig_apx(float x) {
    return fmaf(0.5f, tanh_apx(0.5f * x), 0.5f);
}

__device__ __forceinline__ uint32_t smem_u32(const void* p) {
    uint32_t a;
    asm("{ .reg .u64 t; cvta.to.shared.u64 t, %1; cvt.u32.u64 %0, t; }" : "=r"(a) : "l"(p));
    return a;
}
__device__ __forceinline__ void ldsm_x4(uint32_t r[4], uint32_t addr) {
    asm volatile("ldmatrix.sync.aligned.m8n8.x4.shared.b16 {%0,%1,%2,%3}, [%4];"
                 : "=r"(r[0]), "=r"(r[1]), "=r"(r[2]), "=r"(r[3]) : "r"(addr));
}
__device__ __forceinline__ void mma_bf16(float c[4], const uint32_t a[4],
                                         uint32_t b0, uint32_t b1) {
    asm volatile(
        "mma.sync.aligned.m16n8k16.row.col.f32.bf16.bf16.f32 "
        "{%0,%1,%2,%3}, {%4,%5,%6,%7}, {%8,%9}, {%0,%1,%2,%3};"
        : "+f"(c[0]), "+f"(c[1]), "+f"(c[2]), "+f"(c[3])
        : "r"(a[0]), "r"(a[1]), "r"(a[2]), "r"(a[3]), "r"(b0), "r"(b1));
}
__device__ __forceinline__ float2 bf2f2(uint32_t u) {
    __nv_bfloat162 h = *reinterpret_cast<__nv_bfloat162*>(&u);
    return __bfloat1622float2(h);
}
__device__ __forceinline__ uint32_t tanh_bf16x2(uint32_t x) {
    uint32_t d;
    asm("tanh.approx.bf16x2 %0, %1;" : "=r"(d) : "r"(x));
    return d;
}

// ======================= fused prep (1 launch) ==============================
__global__ void prep_all(const float* __restrict__ Wih_p, const float* __restrict__ bih_p,
                         const float* __restrict__ bhh_p,
                         const float* __restrict__ Wih_h, const float* __restrict__ bih_h,
                         const float* __restrict__ bhh_h,
                         const float* __restrict__ Wih_m, const float* __restrict__ bih_m,
                         const float* __restrict__ bhh_m,
                         const float* __restrict__ Wm,
                         const float* __restrict__ Ws, const float* __restrict__ Wt,
                         __nv_bfloat16* __restrict__ Wp, __nv_bfloat16* __restrict__ Wh,
                         __nv_bfloat16* __restrict__ Wa, __nv_bfloat16* __restrict__ Whm,
                         __nv_bfloat16* __restrict__ Wsb, __nv_bfloat16* __restrict__ Wtb,
                         __nv_bfloat16* __restrict__ WmT,
                         float* __restrict__ bp, float* __restrict__ bh,
                         float* __restrict__ bm)
{
    int idx = blockIdx.x * blockDim.x + threadIdx.x;
    if (idx < 270000) {
        int j = idx / 300, k2 = idx % 300;
        int src = (j < 300) ? j : j + 300;
        Wp[idx] = __float2bfloat16(Wih_p[(size_t)src * 300 + k2]);
    } else if (idx < 540000) {
        int t = idx - 270000; int j = t / 300, k2 = t % 300;
        int src = (j < 300) ? j : j + 300;
        Wh[t] = __float2bfloat16(Wih_h[(size_t)src * 300 + k2]);
    } else if (idx < 810000) {
        int t = idx - 540000; int j = t / 300, k2 = t % 300;
        int src = (j < 300) ? j : j + 300;
        Wa[t] = __float2bfloat16(Wih_m[(size_t)src * 600 + k2]);
    } else if (idx < 1080000) {
        int t = idx - 810000; int j = t / 300, k2 = t % 300;
        int src = (j < 300) ? j : j + 300;
        Whm[t] = __float2bfloat16(Wih_m[(size_t)src * 600 + 300 + k2]);
    } else if (idx < 1170000) {
        int t = idx - 1080000;
        Wsb[t] = __float2bfloat16(Ws[t]);
    } else if (idx < 1260000) {
        int t = idx - 1170000;
        Wtb[t] = __float2bfloat16(Wt[t]);
    } else if (idx < 1350000) {
        int t = idx - 1260000; int d = t / 300, j = t % 300;
        WmT[t] = __float2bfloat16(Wm[(size_t)j * 300 + d]);
    }
    if (idx < 900) {
        int src = (idx < 300) ? idx : idx + 300;
        bp[idx] = bih_p[src] + bhh_p[src];
        bh[idx] = bih_h[src] + bhh_h[src];
        bm[idx] = bih_m[src] + bhh_m[src];
    }
}

// ======================= bf16 tensor-core GEMM core =========================
constexpr int GLDK = 40;
constexpr int GBUF = 128 * GLDK;   // 5120 bf16 per buffer

template <typename AT, typename CT>
__device__ __forceinline__ void gemm_core(
    const AT* __restrict__ A, const int* __restrict__ tok,
    const __nv_bfloat16* __restrict__ B, int Brows,
    CT* __restrict__ C, int N, const float* __restrict__ bias,
    __nv_bfloat16* __restrict__ sm, int mbase, int nbase)
{
    constexpr bool AF32 = (sizeof(AT) == 4);
    const int tid = threadIdx.x;
    const int warp = tid >> 5, lane = tid & 31;
    const int wm = warp >> 2, wn = warp & 3;

    const uint32_t aB[2] = { smem_u32(sm),            smem_u32(sm + GBUF) };
    const uint32_t bB[2] = { smem_u32(sm + 2 * GBUF), smem_u32(sm + 3 * GBUF) };

    int arow_s[4], asrc[4], ac4[4];
    bool bok[4];
#pragma unroll
    for (int p = 0; p < 4; ++p) {
        const int f4 = tid + 256 * p;
        const int row = f4 >> 3;
        arow_s[p] = row;
        ac4[p]    = f4 & 7;
        const int gm = mbase + row;
        asrc[p] = tok ? tok[gm] : gm;
        bok[p]  = (nbase + row) < Brows;
    }

    float acc[4][4][4];
#pragma unroll
    for (int i = 0; i < 4; i++)
#pragma unroll
        for (int n = 0; n < 4; n++)
#pragma unroll
            for (int e = 0; e < 4; e++) acc[i][n][e] = 0.f;

    const int lrow = lane & 15;
    const int lkof = (lane >> 4) << 3;

    float4 vaf[4];
    uint2  vab[4], vbb[4];

    auto load_chunk = [&](int k0) {
#pragma unroll
        for (int p = 0; p < 4; ++p) {
            const int kk = k0 + ac4[p] * 4;
            const bool kv = (kk < 300);
            if (AF32) {
                vaf[p] = kv ? *reinterpret_cast<const float4*>((const float*)A + (size_t)asrc[p] * 300 + kk)
                            : make_float4(0.f, 0.f, 0.f, 0.f);
            } else {
                vab[p] = kv ? *reinterpret_cast<const uint2*>((const __nv_bfloat16*)A + (size_t)asrc[p] * 300 + kk)
                            : make_uint2(0u, 0u);
            }
            vbb[p] = (kv && bok[p])
                ? *reinterpret_cast<const uint2*>(B + (size_t)(nbase + arow_s[p]) * 300 + kk)
                : make_uint2(0u, 0u);
        }
    };
    auto store_chunk = [&](int buf) {
        __nv_bfloat16* Asb = sm + buf * GBUF;
        __nv_bfloat16* Bsb = sm + (2 + buf) * GBUF;
#pragma unroll
        for (int p = 0; p < 4; ++p) {
            const int off = arow_s[p] * GLDK + ac4[p] * 4;
            if (AF32) {
                __nv_bfloat162 alo = __float22bfloat162_rn(make_float2(vaf[p].x, vaf[p].y));
                __nv_bfloat162 ahi = __float22bfloat162_rn(make_float2(vaf[p].z, vaf[p].w));
                *reinterpret_cast<uint2*>(&Asb[off]) =
                    make_uint2(*reinterpret_cast<uint32_t*>(&alo), *reinterpret_cast<uint32_t*>(&ahi));
            } else {
                *reinterpret_cast<uint2*>(&Asb[off]) = vab[p];
            }
            *reinterpret_cast<uint2*>(&Bsb[off]) = vbb[p];
        }
    };

    load_chunk(0);
    store_chunk(0);
    __syncthreads();

#pragma unroll 1
    for (int c = 0; c < 10; ++c) {
        if (c < 9) load_chunk((c + 1) * 32);
        const uint32_t a0 = aB[c & 1], b0 = bB[c & 1];
#pragma unroll
        for (int j = 0; j < 2; ++j) {
            const int kcol = j * 16 + lkof;
            uint32_t af[4][4], bfr[2][4];
#pragma unroll
            for (int i = 0; i < 4; ++i)
                ldsm_x4(af[i], a0 + (uint32_t)(((wm * 64 + i * 16 + lrow) * GLDK + kcol) * 2));
#pragma unroll
            for (int nt = 0; nt < 2; ++nt)
                ldsm_x4(bfr[nt], b0 + (uint32_t)(((wn * 32 + nt * 16 + lrow) * GLDK + kcol) * 2));
#pragma unroll
            for (int i = 0; i < 4; ++i)
#pragma unroll
                for (int n = 0; n < 4; ++n) {
                    const int nt = n >> 1, s = n & 1;
                    mma_bf16(acc[i][n], af[i], bfr[nt][s], bfr[nt][s + 2]);
                }
        }
        if (c < 9) { store_chunk((c + 1) & 1); __syncthreads(); }
    }

#pragma unroll
    for (int i = 0; i < 4; ++i) {
        const int r = mbase + wm * 64 + i * 16 + (lane >> 2);
#pragma unroll
        for (int n = 0; n < 4; ++n) {
            const int col = nbase + wn * 32 + n * 8 + (lane & 3) * 2;
            if (col < N) {
                float2 bv = make_float2(0.f, 0.f);
                if (bias) bv = *reinterpret_cast<const float2*>(bias + col);
                float v0 = acc[i][n][0] + bv.x, v1 = acc[i][n][1] + bv.y;
                float v2 = acc[i][n][2] + bv.x, v3 = acc[i][n][3] + bv.y;
                if (sizeof(CT) == 4) {
                    *reinterpret_cast<float2*>((float*)C + (size_t)r * N + col) = make_float2(v0, v1);
                    *reinterpret_cast<float2*>((float*)C + (size_t)(r + 8) * N + col) = make_float2(v2, v3);
                } else {
                    __nv_bfloat162 lo = __float22bfloat162_rn(make_float2(v0, v1));
                    __nv_bfloat162 hi = __float22bfloat162_rn(make_float2(v2, v3));
                    *reinterpret_cast<uint32_t*>((__nv_bfloat16*)C + (size_t)r * N + col) =
                        *reinterpret_cast<uint32_t*>(&lo);
                    *reinterpret_cast<uint32_t*>((__nv_bfloat16*)C + (size_t)(r + 8) * N + col) =
                        *reinterpret_cast<uint32_t*>(&hi);
                }
            }
        }
    }
}

// encoders: z=0 premise, z=1 hypothesis (f32 gather A, bf16 C, fused bias)
__global__ __launch_bounds__(256, 2)
void gemm_enc(const float* __restrict__ embed,
              const int* __restrict__ tokA, const int* __restrict__ tokB,
              const __nv_bfloat16* __restrict__ WA, const __nv_bfloat16* __restrict__ WB,
              const float* __restrict__ bA, const float* __restrict__ bB2,
              __nv_bfloat16* __restrict__ CA, __nv_bfloat16* __restrict__ CB)
{
    __shared__ __nv_bfloat16 sm[4 * GBUF];
    const int z = blockIdx.z;
    gemm_core<float, __nv_bfloat16>(embed, z ? tokB : tokA, z ? WB : WA, 900,
                                    z ? CB : CA, 900, z ? bB2 : bA, sm,
                                    blockIdx.y * 128, blockIdx.x * 128);
}

// 4 precomputes in one launch (bf16 A, bf16 C)
struct Pre4 {
    const __nv_bfloat16* A[4];
    const __nv_bfloat16* B[4];
    __nv_bfloat16*       C[4];
    const float*         bias[4];
    int                  N[4];
};
__global__ __launch_bounds__(256, 2)
void gemm_pre(Pre4 a)
{
    __shared__ __nv_bfloat16 sm[4 * GBUF];
    const int z = blockIdx.z;
    const int N = a.N[z];
    const int nbase = blockIdx.x * 128;
    if (nbase >= N) return;
    gemm_core<__nv_bfloat16, __nv_bfloat16>(a.A[z], nullptr, a.B[z], N,
                                            a.C[z], N, a.bias[z], sm,
                                            blockIdx.y * 128, nbase);
}

// ======================= lstm0 activation (bf16 gates in) ===================
__global__ void lstm_act2(const __nv_bfloat16* __restrict__ G1,
                          const __nv_bfloat16* __restrict__ G2,
                          __nv_bfloat16* __restrict__ h1, __nv_bfloat16* __restrict__ h2)
{
    int idx = blockIdx.x * blockDim.x + threadIdx.x;
    if (idx >= 8192 * 150) return;
    const __nv_bfloat16* G = blockIdx.y ? G2 : G1;
    __nv_bfloat16* h = blockIdx.y ? h2 : h1;
    int m = idx / 150, j2 = (idx % 150) * 2;
    const uint32_t* g = reinterpret_cast<const uint32_t*>(G + (size_t)m * 900);
    float2 gi = bf2f2(g[j2 / 2]);
    float2 gg = bf2f2(g[(j2 + 300) / 2]);
    float2 go = bf2f2(g[(j2 + 600) / 2]);
    float c0 = sig_apx(gi.x) * tanh_apx(gg.x);
    float c1 = sig_apx(gi.y) * tanh_apx(gg.y);
    float v0 = sig_apx(go.x) * tanh_apx(c0);
    float v1 = sig_apx(go.y) * tanh_apx(c1);
    __nv_bfloat162 o2 = __float22bfloat162_rn(make_float2(v0, v1));
    *reinterpret_cast<uint32_t*>(h + (size_t)m * 300 + j2) = *reinterpret_cast<uint32_t*>(&o2);
}

// ======================= persistent per-batch scan (512 thr) ================
constexpr int SM_WMT = 0;        // 90000 bf16 = 180000
constexpr int SM_SP  = 180000;   // 19200 bf16 = 38400
constexpr int SM_SCR = 218400;   // 1800 f32 = 7200 (A partials; C gates)
constexpr int SM_WE  = 225600;   // 300 f32
constexpr int SM_HM  = 226800;   // 300 f32
constexpr int SM_AL  = 228000;   // 64 f32 (raw e)
constexpr int SM_TM  = 228256;   // 300 bf16 = 600
constexpr int SM_RED = 228856;   // 8 f32
constexpr int SM_ALN = 228896;   // 64 f32 (normalized alpha, 16B aligned)
constexpr int SCAN_SMEM_BYTES = 229152;

__global__ __launch_bounds__(512)
void scan_kernel(const __nv_bfloat16* __restrict__ sproj, const __nv_bfloat16* __restrict__ tproj,
                 const __nv_bfloat16* __restrict__ htpre, const __nv_bfloat16* __restrict__ hsWa,
                 const __nv_bfloat16* __restrict__ WmTg,  const float* __restrict__ w_e,
                 const int* __restrict__ plen_a,  const int* __restrict__ hlen_a,
                 const float* __restrict__ fcw,   const float* __restrict__ fcb,
                 float* __restrict__ out)
{
    extern __shared__ char smraw[];
    __nv_bfloat16* wmt   = reinterpret_cast<__nv_bfloat16*>(smraw + SM_WMT);
    __nv_bfloat16* sp    = reinterpret_cast<__nv_bfloat16*>(smraw + SM_SP);
    float*         scr   = reinterpret_cast<float*>(smraw + SM_SCR);
    float*         we_s  = reinterpret_cast<float*>(smraw + SM_WE);
    float*         hm    = reinterpret_cast<float*>(smraw + SM_HM);
    float*         alpha = reinterpret_cast<float*>(smraw + SM_AL);
    __nv_bfloat16* tm    = reinterpret_cast<__nv_bfloat16*>(smraw + SM_TM);
    float*         red   = reinterpret_cast<float*>(smraw + SM_RED);
    float*         alpn  = reinterpret_cast<float*>(smraw + SM_ALN);

    const int b    = blockIdx.x;
    const int tid  = threadIdx.x;
    const int warp = tid >> 5, lane = tid & 31;

    for (int i = tid; i < 11250; i += 512)
        reinterpret_cast<uint4*>(wmt)[i] = reinterpret_cast<const uint4*>(WmTg)[i];
    const uint4* spg = reinterpret_cast<const uint4*>(sproj + (size_t)b * 19200);
    for (int i = tid; i < 2400; i += 512)
        reinterpret_cast<uint4*>(sp)[i] = spg[i];
    for (int i = tid; i < 300; i += 512) { we_s[i] = w_e[i]; hm[i] = 0.f; }
    const int plen = plen_a[b];
    const int hlen = hlen_a[b];

    // hsWa is k-invariant: 64 rows in registers (column pair per thread)
    uint32_t pre[64];
    if (tid < 450) {
        const uint32_t* hwp = reinterpret_cast<const uint32_t*>(
                                  hsWa + (size_t)b * (64 * 900)) + tid;
#pragma unroll
        for (int p = 0; p < 64; ++p)
            pre[p] = hwp[(size_t)p * 450];
    }
    __syncthreads();

    // w_e pairs for Phase B are step- and row-invariant: registers
    float2 we2[5];
#pragma unroll
    for (int i = 0; i < 5; ++i) {
        const int hp = lane + 32 * i;
        we2[i] = (hp < 150) ? *reinterpret_cast<const float2*>(we_s + 2 * hp)
                            : make_float2(0.f, 0.f);
    }

    for (int k = 0; k < hlen; ++k) {
        // prefetch step-k streams (consumed >2K cycles later)
        uint32_t prh = 0;
        uint2 tkv = make_uint2(0u, 0u);
        if (tid < 450)
            prh = __ldcs(reinterpret_cast<const uint32_t*>(
                      htpre + ((size_t)b * 64 + k) * 900) + tid);
        if (tid < 75)
            tkv = __ldcs(reinterpret_cast<const uint2*>(
                      tproj + ((size_t)b * 64 + k) * 300) + tid);

        // Phase A: m_proj partials = hm @ Wm^T (6 segs x 75 col-quads), d-pairs
        if (k > 0 && tid < 450) {
            const int seg = tid / 75;
            const int jq  = tid % 75;
            const int d0  = seg * 50;
            float4 acc = make_float4(0.f, 0.f, 0.f, 0.f);
#pragma unroll 5
            for (int d = d0; d < d0 + 50; d += 2) {
                const float2 hv = *reinterpret_cast<const float2*>(hm + d);
                const uint2 w0 = *reinterpret_cast<const uint2*>(wmt + d * 300 + jq * 4);
                const uint2 w1 = *reinterpret_cast<const uint2*>(wmt + (d + 1) * 300 + jq * 4);
                float2 a0 = bf2f2(w0.x), a1 = bf2f2(w0.y);
                float2 b0 = bf2f2(w1.x), b1 = bf2f2(w1.y);
                acc.x = fmaf(hv.x, a0.x, fmaf(hv.y, b0.x, acc.x));
                acc.y = fmaf(hv.x, a0.y, fmaf(hv.y, b0.y, acc.y));
                acc.z = fmaf(hv.x, a1.x, fmaf(hv.y, b1.x, acc.z));
                acc.w = fmaf(hv.x, a1.y, fmaf(hv.y, b1.y, acc.w));
            }
            reinterpret_cast<float4*>(scr)[seg * 75 + jq] = acc;
        }
        __syncthreads();

        // reduce partials -> mp; tm = bf16(tk + mp); tk already in regs
        if (tid < 75) {
            float4 m = make_float4(0.f, 0.f, 0.f, 0.f);
            if (k > 0) {
#pragma unroll
                for (int s = 0; s < 6; ++s) {
                    float4 a = reinterpret_cast<float4*>(scr)[s * 75 + tid];
                    m.x += a.x; m.y += a.y; m.z += a.z; m.w += a.w;
                }
            }
            float2 t0 = bf2f2(tkv.x), t1 = bf2f2(tkv.y);
            __nv_bfloat162 p0 = __float22bfloat162_rn(make_float2(m.x + t0.x, m.y + t0.y));
            __nv_bfloat162 p1 = __float22bfloat162_rn(make_float2(m.z + t1.x, m.w + t1.y));
            *reinterpret_cast<uint2*>(tm + 4 * tid) =
                make_uint2(*reinterpret_cast<uint32_t*>(&p0), *reinterpret_cast<uint32_t*>(&p1));
        }
        __syncthreads();

        // Phase B: e[p] = w_e . tanh(sp[p] + tm); tm slices cached per step
        const uint32_t* tmu = reinterpret_cast<const uint32_t*>(tm);
        uint32_t tmv[5];
#pragma unroll
        for (int i = 0; i < 5; ++i) {
            const int hp = lane + 32 * i;
            tmv[i] = (hp < 150) ? tmu[hp] : 0u;
        }
        for (int p = warp; p < plen; p += 16) {
            const uint32_t* srow = reinterpret_cast<const uint32_t*>(sp + p * 300);
            float acc = 0.f;
#pragma unroll
            for (int i = 0; i < 5; ++i) {
                const int hp = lane + 32 * i;
                if (hp < 150) {
                    uint32_t s2 = srow[hp];
                    __nv_bfloat162 x2 = __hadd2(*reinterpret_cast<__nv_bfloat162*>(&s2),
                                                *reinterpret_cast<__nv_bfloat162*>(&tmv[i]));
                    uint32_t th = tanh_bf16x2(*reinterpret_cast<uint32_t*>(&x2));
                    float2 tf = bf2f2(th);
                    acc = fmaf(we2[i].x, tf.x, acc);
                    acc = fmaf(we2[i].y, tf.y, acc);
                }
            }
#pragma unroll
            for (int o = 16; o > 0; o >>= 1) acc += __shfl_xor_sync(0xffffffffu, acc, o);
            if (lane == 0) alpha[p] = acc;
        }
        __syncthreads();

        // softmax: ALL warps compute redundantly (identical ops, benign races),
        // each warp writes all 64 alpn entries -> no block barrier before C.
        {
            float e0 = (lane < plen) ? alpha[lane] : -FLT_MAX;
            float e1 = (lane + 32 < plen) ? alpha[lane + 32] : -FLT_MAX;
            float mx = fmaxf(e0, e1);
#pragma unroll
            for (int o = 16; o > 0; o >>= 1) mx = fmaxf(mx, __shfl_xor_sync(0xffffffffu, mx, o));
            float x0 = (lane < plen) ? __expf(e0 - mx) : 0.f;
            float x1 = (lane + 32 < plen) ? __expf(e1 - mx) : 0.f;
            float s = x0 + x1;
#pragma unroll
            for (int o = 16; o > 0; o >>= 1) s += __shfl_xor_sync(0xffffffffu, s, o);
            float inv = 1.f / s;
            alpn[lane]      = x0 * inv;
            alpn[lane + 32] = x1 * inv;
            __syncwarp();
        }

        // Phase C: gates = sum_p alpn[p]*pre[p] + htpre(+biasM); dual accs;
        // uniform early exit at plen (alpn is exactly 0 beyond plen)
        if (tid < 450) {
            float2 acc0 = bf2f2(prh);
            float2 acc1 = make_float2(0.f, 0.f);
            const float4* al4 = reinterpret_cast<const float4*>(alpn);
#pragma unroll
            for (int q = 0; q < 16; ++q) {
                if (4 * q >= plen) break;
                const float4 av = al4[q];
                float2 w;
                w = bf2f2(pre[4 * q + 0]);
                acc0.x = fmaf(av.x, w.x, acc0.x); acc0.y = fmaf(av.x, w.y, acc0.y);
                w = bf2f2(pre[4 * q + 1]);
                acc1.x = fmaf(av.y, w.x, acc1.x); acc1.y = fmaf(av.y, w.y, acc1.y);
                w = bf2f2(pre[4 * q + 2]);
                acc0.x = fmaf(av.z, w.x, acc0.x); acc0.y = fmaf(av.z, w.y, acc0.y);
                w = bf2f2(pre[4 * q + 3]);
                acc1.x = fmaf(av.w, w.x, acc1.x); acc1.y = fmaf(av.w, w.y, acc1.y);
            }
            scr[2 * tid]     = acc0.x + acc1.x;
            scr[2 * tid + 1] = acc0.y + acc1.y;
        }
        __syncthreads();

        // Phase D: h_m update (MUFU approx)
        if (tid < 300) {
            float gi = scr[tid];
            float gg = scr[tid + 300];
            float go = scr[tid + 600];
            float c  = sig_apx(gi) * tanh_apx(gg);
            hm[tid]  = sig_apx(go) * tanh_apx(c);
        }
        __syncthreads();
    }

    // after the loop hm == h_m[hlen-1]
    if (warp < 3) {
        float acc = 0.f;
        for (int h = lane; h < 300; h += 32) acc += hm[h] * fcw[warp * 300 + h];
#pragma unroll
        for (int o = 16; o > 0; o >>= 1) acc += __shfl_xor_sync(0xffffffffu, acc, o);
        if (lane == 0) red[warp] = acc + fcb[warp];
    }
    __syncthreads();
    if (tid == 0) {
        float l0 = red[0], l1 = red[1], l2 = red[2];
        float mx = fmaxf(l0, fmaxf(l1, l2));
        float e0 = expf(l0 - mx), e1 = expf(l1 - mx), e2 = expf(l2 - mx);
        float inv = 1.f / (e0 + e1 + e2);
        out[b * 3 + 0] = e0 * inv;
        out[b * 3 + 1] = e1 * inv;
        out[b * 3 + 2] = e2 * inv;
    }
}

// ---------------------------------------------------------------------------
extern "C" void kernel_launch(void* const* d_in, const int* in_sizes, int n_in,
                              void* d_out, int out_size)
{
    const int*   premise = (const int*)  d_in[0];
    const int*   plen    = (const int*)  d_in[1];
    const int*   hyp     = (const int*)  d_in[2];
    const int*   hlen    = (const int*)  d_in[3];
    const float* embed   = (const float*)d_in[4];
    const float* w_e     = (const float*)d_in[5];
    const float* W_s     = (const float*)d_in[6];
    const float* W_t     = (const float*)d_in[7];
    const float* W_m     = (const float*)d_in[8];
    const float* fc_w    = (const float*)d_in[9];
    const float* fc_b    = (const float*)d_in[10];
    const float* Wih_p   = (const float*)d_in[11];
    const float* bih_p   = (const float*)d_in[13];
    const float* bhh_p   = (const float*)d_in[14];
    const float* Wih_h   = (const float*)d_in[15];
    const float* bih_h   = (const float*)d_in[17];
    const float* bhh_h   = (const float*)d_in[18];
    const float* Wih_m   = (const float*)d_in[19];
    const float* bih_m   = (const float*)d_in[21];
    const float* bhh_m   = (const float*)d_in[22];

    float* buf = nullptr;
    cudaGetSymbolAddress((void**)&buf, g_buf);
    __nv_bfloat16*  gates1 = (__nv_bfloat16*)(buf + OFF_GATES1);
    __nv_bfloat16*  gates2 = (__nv_bfloat16*)(buf + OFF_GATES2);
    __nv_bfloat16*  hs     = (__nv_bfloat16*)(buf + OFF_HS);
    __nv_bfloat16*  ht     = (__nv_bfloat16*)(buf + OFF_HT);
    __nv_bfloat16*  sprojp = (__nv_bfloat16*)(buf + OFF_SPROJ);
    __nv_bfloat16*  tprojp = (__nv_bfloat16*)(buf + OFF_TPROJ);
    __nv_bfloat16*  htprep = (__nv_bfloat16*)(buf + OFF_HTPRE);
    __nv_bfloat16*  hsWap  = (__nv_bfloat16*)(buf + OFF_HSWA);
    __nv_bfloat16*  Wp     = (__nv_bfloat16*)(buf + OFF_WPB);
    __nv_bfloat16*  Wh     = (__nv_bfloat16*)(buf + OFF_WHB);
    __nv_bfloat16*  Wa     = (__nv_bfloat16*)(buf + OFF_WAB);
    __nv_bfloat16*  Whm    = (__nv_bfloat16*)(buf + OFF_WHMB);
    __nv_bfloat16*  Wsb    = (__nv_bfloat16*)(buf + OFF_WSB);
    __nv_bfloat16*  Wtb    = (__nv_bfloat16*)(buf + OFF_WTB);
    __nv_bfloat16*  WmT    = (__nv_bfloat16*)(buf + OFF_WMTB);
    float* bp = buf + OFF_BP;
    float* bh = buf + OFF_BH;
    float* bm = buf + OFF_BM;

    prep_all<<<(1350000 + 255) / 256, 256>>>(Wih_p, bih_p, bhh_p,
                                             Wih_h, bih_h, bhh_h,
                                             Wih_m, bih_m, bhh_m,
                                             W_m, W_s, W_t,
                                             Wp, Wh, Wa, Whm, Wsb, Wtb, WmT,
                                             bp, bh, bm);

    gemm_enc<<<dim3(8, 64, 2), 256>>>(embed, premise, hyp, Wp, Wh, bp, bh,
                                      gates1, gates2);
    lstm_act2<<<dim3((8192 * 150 + 255) / 256, 2), 256>>>(gates1, gates2, hs, ht);

    Pre4 pa;
    pa.A[0] = hs;  pa.B[0] = Wa;  pa.C[0] = hsWap;  pa.bias[0] = nullptr; pa.N[0] = 900;
    pa.A[1] = ht;  pa.B[1] = Whm; pa.C[1] = htprep; pa.bias[1] = bm;      pa.N[1] = 900;
    pa.A[2] = hs;  pa.B[2] = Wsb; pa.C[2] = sprojp; pa.bias[2] = nullptr; pa.N[2] = 300;
    pa.A[3] = ht;  pa.B[3] = Wtb; pa.C[3] = tprojp; pa.bias[3] = nullptr; pa.N[3] = 300;
    gemm_pre<<<dim3(8, 64, 4), 256>>>(pa);

    cudaFuncSetAttribute(scan_kernel, cudaFuncAttributeMaxDynamicSharedMemorySize,
                         SCAN_SMEM_BYTES);
    scan_kernel<<<128, 512, SCAN_SMEM_BYTES>>>(sprojp, tprojp, htprep, hsWap, WmT,
                                               w_e, plen, hlen, fc_w, fc_b,
                                               (float*)d_out);
}

// round 17
// speedup vs baseline: 1.0277x; 1.0129x over previous
#include <cuda_runtime.h>
#include <cuda_bf16.h>
#include <math.h>
#include <float.h>
#include <stdint.h>

// ---------------------------------------------------------------------------
// MatchLSTM: B=128, P=K=64, E=H=300, V=50000, C=3
//  GEMMs: bf16 mma.sync.m16n8k16 + ldmatrix, double-buffered SMEM, fused bias;
//         embeddings pre-gathered to bf16 (all GEMMs on the bf16-A path).
//  Scan: 512 thr/block; WmT in SMEM (paired-row LDS.128 layout); hsWa in regs;
//  tproj/htpre prefetch; all-warp softmax; Phase-C plen early-exit.
// ---------------------------------------------------------------------------

// offsets in f32 units
constexpr size_t OFF_GATES1 = 0;                        // 8192*900 bf16
constexpr size_t OFF_GATES2 = OFF_GATES1 + 3686400;     // 8192*900 bf16
constexpr size_t OFF_HS     = OFF_GATES2 + 3686400;     // 8192*300 bf16
constexpr size_t OFF_HT     = OFF_HS     + 1228800;
constexpr size_t OFF_SPROJ  = OFF_HT     + 1228800;     // 8192*300 bf16
constexpr size_t OFF_TPROJ  = OFF_SPROJ  + 1228800;     // 8192*300 bf16
constexpr size_t OFF_HTPRE  = OFF_TPROJ  + 1228800;     // 8192*900 bf16 (+biasM)
constexpr size_t OFF_HSWA   = OFF_HTPRE  + 3686400;     // 8192*900 bf16
constexpr size_t OFF_EMBP   = OFF_HSWA   + 3686400;     // 8192*300 bf16
constexpr size_t OFF_EMBH   = OFF_EMBP   + 1228800;     // 8192*300 bf16
constexpr size_t OFF_WPB    = OFF_EMBH   + 1228800;     // 900*300 bf16
constexpr size_t OFF_WHB    = OFF_WPB    + 135000;
constexpr size_t OFF_WAB    = OFF_WHB    + 135000;
constexpr size_t OFF_WHMB   = OFF_WAB    + 135000;
constexpr size_t OFF_WSB    = OFF_WHMB   + 135000;      // 300*300 bf16
constexpr size_t OFF_WTB    = OFF_WSB    + 45000;
constexpr size_t OFF_WMTB   = OFF_WTB    + 45000;       // 300*300 bf16 (paired)
constexpr size_t OFF_BP     = OFF_WMTB   + 45000;       // 900 f32
constexpr size_t OFF_BH     = OFF_BP + 900;
constexpr size_t OFF_BM     = OFF_BH + 900;
constexpr size_t BUF_TOTAL  = OFF_BM + 900;

__device__ __align__(16) float g_buf[BUF_TOTAL];

__device__ __forceinline__ float tanh_apx(float x) {
    float y; asm("tanh.approx.f32 %0, %1;" : "=f"(y) : "f"(x)); return y;
}
__device__ __forceinline__ float sig_apx(float x) {
    return fmaf(0.5f, tanh_apx(0.5f * x), 0.5f);
}

__device__ __forceinline__ uint32_t smem_u32(const void* p) {
    uint32_t a;
    asm("{ .reg .u64 t; cvta.to.shared.u64 t, %1; cvt.u32.u64 %0, t; }" : "=r"(a) : "l"(p));
    return a;
}
__device__ __forceinline__ void ldsm_x4(uint32_t r[4], uint32_t addr) {
    asm volatile("ldmatrix.sync.aligned.m8n8.x4.shared.b16 {%0,%1,%2,%3}, [%4];"
                 : "=r"(r[0]), "=r"(r[1]), "=r"(r[2]), "=r"(r[3]) : "r"(addr));
}
__device__ __forceinline__ void mma_bf16(float c[4], const uint32_t a[4],
                                         uint32_t b0, uint32_t b1) {
    asm volatile(
        "mma.sync.aligned.m16n8k16.row.col.f32.bf16.bf16.f32 "
        "{%0,%1,%2,%3}, {%4,%5,%6,%7}, {%8,%9}, {%0,%1,%2,%3};"
        : "+f"(c[0]), "+f"(c[1]), "+f"(c[2]), "+f"(c[3])
        : "r"(a[0]), "r"(a[1]), "r"(a[2]), "r"(a[3]), "r"(b0), "r"(b1));
}
__device__ __forceinline__ float2 bf2f2(uint32_t u) {
    __nv_bfloat162 h = *reinterpret_cast<__nv_bfloat162*>(&u);
    return __bfloat1622float2(h);
}
__device__ __forceinline__ uint32_t tanh_bf16x2(uint32_t x) {
    uint32_t d;
    asm("tanh.approx.bf16x2 %0, %1;" : "=r"(d) : "r"(x));
    return d;
}

// ======================= fused prep (1 launch) ==============================
// WmT stored in paired-row layout: rows (d,d+1) x col-quad (j>>2) packed as
// 8 contiguous bf16 (16B): idx = ((d>>1)*75 + (j>>2))*8 + (d&1)*4 + (j&3)
__global__ void prep_all(const float* __restrict__ Wih_p, const float* __restrict__ bih_p,
                         const float* __restrict__ bhh_p,
                         const float* __restrict__ Wih_h, const float* __restrict__ bih_h,
                         const float* __restrict__ bhh_h,
                         const float* __restrict__ Wih_m, const float* __restrict__ bih_m,
                         const float* __restrict__ bhh_m,
                         const float* __restrict__ Wm,
                         const float* __restrict__ Ws, const float* __restrict__ Wt,
                         __nv_bfloat16* __restrict__ Wp, __nv_bfloat16* __restrict__ Wh,
                         __nv_bfloat16* __restrict__ Wa, __nv_bfloat16* __restrict__ Whm,
                         __nv_bfloat16* __restrict__ Wsb, __nv_bfloat16* __restrict__ Wtb,
                         __nv_bfloat16* __restrict__ WmT,
                         float* __restrict__ bp, float* __restrict__ bh,
                         float* __restrict__ bm)
{
    int idx = blockIdx.x * blockDim.x + threadIdx.x;
    if (idx < 270000) {
        int j = idx / 300, k2 = idx % 300;
        int src = (j < 300) ? j : j + 300;
        Wp[idx] = __float2bfloat16(Wih_p[(size_t)src * 300 + k2]);
    } else if (idx < 540000) {
        int t = idx - 270000; int j = t / 300, k2 = t % 300;
        int src = (j < 300) ? j : j + 300;
        Wh[t] = __float2bfloat16(Wih_h[(size_t)src * 300 + k2]);
    } else if (idx < 810000) {
        int t = idx - 540000; int j = t / 300, k2 = t % 300;
        int src = (j < 300) ? j : j + 300;
        Wa[t] = __float2bfloat16(Wih_m[(size_t)src * 600 + k2]);
    } else if (idx < 1080000) {
        int t = idx - 810000; int j = t / 300, k2 = t % 300;
        int src = (j < 300) ? j : j + 300;
        Whm[t] = __float2bfloat16(Wih_m[(size_t)src * 600 + 300 + k2]);
    } else if (idx < 1170000) {
        int t = idx - 1080000;
        Wsb[t] = __float2bfloat16(Ws[t]);
    } else if (idx < 1260000) {
        int t = idx - 1170000;
        Wtb[t] = __float2bfloat16(Wt[t]);
    } else if (idx < 1350000) {
        int t = idx - 1260000; int d = t / 300, j = t % 300;
        int dst = ((d >> 1) * 75 + (j >> 2)) * 8 + (d & 1) * 4 + (j & 3);
        WmT[dst] = __float2bfloat16(Wm[(size_t)j * 300 + d]);
    }
    if (idx < 900) {
        int src = (idx < 300) ? idx : idx + 300;
        bp[idx] = bih_p[src] + bhh_p[src];
        bh[idx] = bih_h[src] + bhh_h[src];
        bm[idx] = bih_m[src] + bhh_m[src];
    }
}

// ======================= embed gather -> bf16 (1 launch) ====================
__global__ void gather_embed(const float* __restrict__ embed,
                             const int* __restrict__ tokA, const int* __restrict__ tokB,
                             __nv_bfloat16* __restrict__ outA,
                             __nv_bfloat16* __restrict__ outB)
{
    int idx = blockIdx.x * blockDim.x + threadIdx.x;
    if (idx >= 2 * 8192 * 150) return;
    const bool second = idx >= 8192 * 150;
    const int t = second ? idx - 8192 * 150 : idx;
    const int m = t / 150, j2 = (t % 150) * 2;
    const int* tok = second ? tokB : tokA;
    __nv_bfloat16* out = second ? outB : outA;
    const float2 v = *reinterpret_cast<const float2*>(embed + (size_t)tok[m] * 300 + j2);
    __nv_bfloat162 h2 = __float22bfloat162_rn(v);
    *reinterpret_cast<uint32_t*>(out + (size_t)m * 300 + j2) = *reinterpret_cast<uint32_t*>(&h2);
}

// ======================= bf16 tensor-core GEMM core =========================
constexpr int GLDK = 40;
constexpr int GBUF = 128 * GLDK;   // 5120 bf16 per buffer

__device__ __forceinline__ void gemm_core_bb(
    const __nv_bfloat16* __restrict__ A,
    const __nv_bfloat16* __restrict__ B, int Brows,
    __nv_bfloat16* __restrict__ C, int N, const float* __restrict__ bias,
    __nv_bfloat16* __restrict__ sm, int mbase, int nbase)
{
    const int tid = threadIdx.x;
    const int warp = tid >> 5, lane = tid & 31;
    const int wm = warp >> 2, wn = warp & 3;

    const uint32_t aB[2] = { smem_u32(sm),            smem_u32(sm + GBUF) };
    const uint32_t bB[2] = { smem_u32(sm + 2 * GBUF), smem_u32(sm + 3 * GBUF) };

    int arow_s[4], ac4[4];
    bool bok[4];
#pragma unroll
    for (int p = 0; p < 4; ++p) {
        const int f4 = tid + 256 * p;
        const int row = f4 >> 3;
        arow_s[p] = row;
        ac4[p]    = f4 & 7;
        bok[p]  = (nbase + row) < Brows;
    }

    float acc[4][4][4];
#pragma unroll
    for (int i = 0; i < 4; i++)
#pragma unroll
        for (int n = 0; n < 4; n++)
#pragma unroll
            for (int e = 0; e < 4; e++) acc[i][n][e] = 0.f;

    const int lrow = lane & 15;
    const int lkof = (lane >> 4) << 3;

    uint2 vab[4], vbb[4];

    auto load_chunk = [&](int k0) {
#pragma unroll
        for (int p = 0; p < 4; ++p) {
            const int kk = k0 + ac4[p] * 4;
            const bool kv = (kk < 300);
            vab[p] = kv ? *reinterpret_cast<const uint2*>(A + (size_t)(mbase + arow_s[p]) * 300 + kk)
                        : make_uint2(0u, 0u);
            vbb[p] = (kv && bok[p])
                ? *reinterpret_cast<const uint2*>(B + (size_t)(nbase + arow_s[p]) * 300 + kk)
                : make_uint2(0u, 0u);
        }
    };
    auto store_chunk = [&](int buf) {
        __nv_bfloat16* Asb = sm + buf * GBUF;
        __nv_bfloat16* Bsb = sm + (2 + buf) * GBUF;
#pragma unroll
        for (int p = 0; p < 4; ++p) {
            const int off = arow_s[p] * GLDK + ac4[p] * 4;
            *reinterpret_cast<uint2*>(&Asb[off]) = vab[p];
            *reinterpret_cast<uint2*>(&Bsb[off]) = vbb[p];
        }
    };

    load_chunk(0);
    store_chunk(0);
    __syncthreads();

#pragma unroll 1
    for (int c = 0; c < 10; ++c) {
        if (c < 9) load_chunk((c + 1) * 32);
        const uint32_t a0 = aB[c & 1], b0 = bB[c & 1];
#pragma unroll
        for (int j = 0; j < 2; ++j) {
            const int kcol = j * 16 + lkof;
            uint32_t af[4][4], bfr[2][4];
#pragma unroll
            for (int i = 0; i < 4; ++i)
                ldsm_x4(af[i], a0 + (uint32_t)(((wm * 64 + i * 16 + lrow) * GLDK + kcol) * 2));
#pragma unroll
            for (int nt = 0; nt < 2; ++nt)
                ldsm_x4(bfr[nt], b0 + (uint32_t)(((wn * 32 + nt * 16 + lrow) * GLDK + kcol) * 2));
#pragma unroll
            for (int i = 0; i < 4; ++i)
#pragma unroll
                for (int n = 0; n < 4; ++n) {
                    const int nt = n >> 1, s = n & 1;
                    mma_bf16(acc[i][n], af[i], bfr[nt][s], bfr[nt][s + 2]);
                }
        }
        if (c < 9) { store_chunk((c + 1) & 1); __syncthreads(); }
    }

#pragma unroll
    for (int i = 0; i < 4; ++i) {
        const int r = mbase + wm * 64 + i * 16 + (lane >> 2);
#pragma unroll
        for (int n = 0; n < 4; ++n) {
            const int col = nbase + wn * 32 + n * 8 + (lane & 3) * 2;
            if (col < N) {
                float2 bv = make_float2(0.f, 0.f);
                if (bias) bv = *reinterpret_cast<const float2*>(bias + col);
                float v0 = acc[i][n][0] + bv.x, v1 = acc[i][n][1] + bv.y;
                float v2 = acc[i][n][2] + bv.x, v3 = acc[i][n][3] + bv.y;
                __nv_bfloat162 lo = __float22bfloat162_rn(make_float2(v0, v1));
                __nv_bfloat162 hi = __float22bfloat162_rn(make_float2(v2, v3));
                *reinterpret_cast<uint32_t*>(C + (size_t)r * N + col) =
                    *reinterpret_cast<uint32_t*>(&lo);
                *reinterpret_cast<uint32_t*>(C + (size_t)(r + 8) * N + col) =
                    *reinterpret_cast<uint32_t*>(&hi);
            }
        }
    }
}

// up to 4 GEMMs in one launch (bf16 A, bf16 C)
struct Pre4 {
    const __nv_bfloat16* A[4];
    const __nv_bfloat16* B[4];
    __nv_bfloat16*       C[4];
    const float*         bias[4];
    int                  N[4];
};
__global__ __launch_bounds__(256, 2)
void gemm_pre(Pre4 a)
{
    __shared__ __nv_bfloat16 sm[4 * GBUF];
    const int z = blockIdx.z;
    const int N = a.N[z];
    const int nbase = blockIdx.x * 128;
    if (nbase >= N) return;
    gemm_core_bb(a.A[z], a.B[z], N, a.C[z], N, a.bias[z], sm,
                 blockIdx.y * 128, nbase);
}

// ======================= lstm0 activation (bf16 gates in) ===================
__global__ void lstm_act2(const __nv_bfloat16* __restrict__ G1,
                          const __nv_bfloat16* __restrict__ G2,
                          __nv_bfloat16* __restrict__ h1, __nv_bfloat16* __restrict__ h2)
{
    int idx = blockIdx.x * blockDim.x + threadIdx.x;
    if (idx >= 8192 * 150) return;
    const __nv_bfloat16* G = blockIdx.y ? G2 : G1;
    __nv_bfloat16* h = blockIdx.y ? h2 : h1;
    int m = idx / 150, j2 = (idx % 150) * 2;
    const uint32_t* g = reinterpret_cast<const uint32_t*>(G + (size_t)m * 900);
    float2 gi = bf2f2(g[j2 / 2]);
    float2 gg = bf2f2(g[(j2 + 300) / 2]);
    float2 go = bf2f2(g[(j2 + 600) / 2]);
    float c0 = sig_apx(gi.x) * tanh_apx(gg.x);
    float c1 = sig_apx(gi.y) * tanh_apx(gg.y);
    float v0 = sig_apx(go.x) * tanh_apx(c0);
    float v1 = sig_apx(go.y) * tanh_apx(c1);
    __nv_bfloat162 o2 = __float22bfloat162_rn(make_float2(v0, v1));
    *reinterpret_cast<uint32_t*>(h + (size_t)m * 300 + j2) = *reinterpret_cast<uint32_t*>(&o2);
}

// ======================= persistent per-batch scan (512 thr) ================
constexpr int SM_WMT = 0;        // 90000 bf16 = 180000 (paired-row layout)
constexpr int SM_SP  = 180000;   // 19200 bf16 = 38400
constexpr int SM_SCR = 218400;   // 1800 f32 = 7200 (A partials; C gates)
constexpr int SM_WE  = 225600;   // 300 f32
constexpr int SM_HM  = 226800;   // 300 f32
constexpr int SM_AL  = 228000;   // 64 f32 (raw e)
constexpr int SM_TM  = 228256;   // 300 bf16 = 600
constexpr int SM_RED = 228856;   // 8 f32
constexpr int SM_ALN = 228896;   // 64 f32 (normalized alpha, 16B aligned)
constexpr int SCAN_SMEM_BYTES = 229152;

__global__ __launch_bounds__(512)
void scan_kernel(const __nv_bfloat16* __restrict__ sproj, const __nv_bfloat16* __restrict__ tproj,
                 const __nv_bfloat16* __restrict__ htpre, const __nv_bfloat16* __restrict__ hsWa,
                 const __nv_bfloat16* __restrict__ WmTg,  const float* __restrict__ w_e,
                 const int* __restrict__ plen_a,  const int* __restrict__ hlen_a,
                 const float* __restrict__ fcw,   const float* __restrict__ fcb,
                 float* __restrict__ out)
{
    extern __shared__ char smraw[];
    __nv_bfloat16* wmt   = reinterpret_cast<__nv_bfloat16*>(smraw + SM_WMT);
    __nv_bfloat16* sp    = reinterpret_cast<__nv_bfloat16*>(smraw + SM_SP);
    float*         scr   = reinterpret_cast<float*>(smraw + SM_SCR);
    float*         we_s  = reinterpret_cast<float*>(smraw + SM_WE);
    float*         hm    = reinterpret_cast<float*>(smraw + SM_HM);
    float*         alpha = reinterpret_cast<float*>(smraw + SM_AL);
    __nv_bfloat16* tm    = reinterpret_cast<__nv_bfloat16*>(smraw + SM_TM);
    float*         red   = reinterpret_cast<float*>(smraw + SM_RED);
    float*         alpn  = reinterpret_cast<float*>(smraw + SM_ALN);

    const int b    = blockIdx.x;
    const int tid  = threadIdx.x;
    const int warp = tid >> 5, lane = tid & 31;

    for (int i = tid; i < 11250; i += 512)
        reinterpret_cast<uint4*>(wmt)[i] = reinterpret_cast<const uint4*>(WmTg)[i];
    const uint4* spg = reinterpret_cast<const uint4*>(sproj + (size_t)b * 19200);
    for (int i = tid; i < 2400; i += 512)
        reinterpret_cast<uint4*>(sp)[i] = spg[i];
    for (int i = tid; i < 300; i += 512) { we_s[i] = w_e[i]; hm[i] = 0.f; }
    const int plen = plen_a[b];
    const int hlen = hlen_a[b];

    // hsWa is k-invariant: 64 rows in registers (column pair per thread)
    uint32_t pre[64];
    if (tid < 450) {
        const uint32_t* hwp = reinterpret_cast<const uint32_t*>(
                                  hsWa + (size_t)b * (64 * 900)) + tid;
#pragma unroll
        for (int p = 0; p < 64; ++p)
            pre[p] = hwp[(size_t)p * 450];
    }
    __syncthreads();

    // w_e pairs for Phase B are step- and row-invariant: registers
    float2 we2[5];
#pragma unroll
    for (int i = 0; i < 5; ++i) {
        const int hp = lane + 32 * i;
        we2[i] = (hp < 150) ? *reinterpret_cast<const float2*>(we_s + 2 * hp)
                            : make_float2(0.f, 0.f);
    }

    for (int k = 0; k < hlen; ++k) {
        // prefetch step-k streams (consumed >2K cycles later)
        uint32_t prh = 0;
        uint2 tkv = make_uint2(0u, 0u);
        if (tid < 450)
            prh = __ldcs(reinterpret_cast<const uint32_t*>(
                      htpre + ((size_t)b * 64 + k) * 900) + tid);
        if (tid < 75)
            tkv = __ldcs(reinterpret_cast<const uint2*>(
                      tproj + ((size_t)b * 64 + k) * 300) + tid);

        // Phase A: m_proj partials = hm @ Wm^T (6 segs x 75 col-quads);
        // paired-row layout -> one LDS.128 per 2-d step
        if (k > 0 && tid < 450) {
            const int seg = tid / 75;
            const int jq  = tid % 75;
            const int d0  = seg * 50;
            const uint4* wrow = reinterpret_cast<const uint4*>(wmt) + (d0 >> 1) * 75 + jq;
            const float* hmp = hm + d0;
            float4 acc = make_float4(0.f, 0.f, 0.f, 0.f);
#pragma unroll 5
            for (int i = 0; i < 25; ++i) {
                const float2 hv = *reinterpret_cast<const float2*>(hmp + 2 * i);
                const uint4 w = wrow[(size_t)i * 75];
                float2 a0 = bf2f2(w.x), a1 = bf2f2(w.y);
                float2 b0 = bf2f2(w.z), b1 = bf2f2(w.w);
                acc.x = fmaf(hv.x, a0.x, fmaf(hv.y, b0.x, acc.x));
                acc.y = fmaf(hv.x, a0.y, fmaf(hv.y, b0.y, acc.y));
                acc.z = fmaf(hv.x, a1.x, fmaf(hv.y, b1.x, acc.z));
                acc.w = fmaf(hv.x, a1.y, fmaf(hv.y, b1.y, acc.w));
            }
            reinterpret_cast<float4*>(scr)[seg * 75 + jq] = acc;
        }
        __syncthreads();

        // reduce partials -> mp; tm = bf16(tk + mp); tk already in regs
        if (tid < 75) {
            float4 m = make_float4(0.f, 0.f, 0.f, 0.f);
            if (k > 0) {
#pragma unroll
                for (int s = 0; s < 6; ++s) {
                    float4 a = reinterpret_cast<float4*>(scr)[s * 75 + tid];
                    m.x += a.x; m.y += a.y; m.z += a.z; m.w += a.w;
                }
            }
            float2 t0 = bf2f2(tkv.x), t1 = bf2f2(tkv.y);
            __nv_bfloat162 p0 = __float22bfloat162_rn(make_float2(m.x + t0.x, m.y + t0.y));
            __nv_bfloat162 p1 = __float22bfloat162_rn(make_float2(m.z + t1.x, m.w + t1.y));
            *reinterpret_cast<uint2*>(tm + 4 * tid) =
                make_uint2(*reinterpret_cast<uint32_t*>(&p0), *reinterpret_cast<uint32_t*>(&p1));
        }
        __syncthreads();

        // Phase B: e[p] = w_e . tanh(sp[p] + tm); tm slices cached per step
        const uint32_t* tmu = reinterpret_cast<const uint32_t*>(tm);
        uint32_t tmv[5];
#pragma unroll
        for (int i = 0; i < 5; ++i) {
            const int hp = lane + 32 * i;
            tmv[i] = (hp < 150) ? tmu[hp] : 0u;
        }
        for (int p = warp; p < plen; p += 16) {
            const uint32_t* srow = reinterpret_cast<const uint32_t*>(sp + p * 300);
            float acc = 0.f;
#pragma unroll
            for (int i = 0; i < 5; ++i) {
                const int hp = lane + 32 * i;
                if (hp < 150) {
                    uint32_t s2 = srow[hp];
                    __nv_bfloat162 x2 = __hadd2(*reinterpret_cast<__nv_bfloat162*>(&s2),
                                                *reinterpret_cast<__nv_bfloat162*>(&tmv[i]));
                    uint32_t th = tanh_bf16x2(*reinterpret_cast<uint32_t*>(&x2));
                    float2 tf = bf2f2(th);
                    acc = fmaf(we2[i].x, tf.x, acc);
                    acc = fmaf(we2[i].y, tf.y, acc);
                }
            }
#pragma unroll
            for (int o = 16; o > 0; o >>= 1) acc += __shfl_xor_sync(0xffffffffu, acc, o);
            if (lane == 0) alpha[p] = acc;
        }
        __syncthreads();

        // softmax: ALL warps compute redundantly (identical ops, benign races),
        // each warp writes all 64 alpn entries -> no block barrier before C.
        {
            float e0 = (lane < plen) ? alpha[lane] : -FLT_MAX;
            float e1 = (lane + 32 < plen) ? alpha[lane + 32] : -FLT_MAX;
            float mx = fmaxf(e0, e1);
#pragma unroll
            for (int o = 16; o > 0; o >>= 1) mx = fmaxf(mx, __shfl_xor_sync(0xffffffffu, mx, o));
            float x0 = (lane < plen) ? __expf(e0 - mx) : 0.f;
            float x1 = (lane + 32 < plen) ? __expf(e1 - mx) : 0.f;
            float s = x0 + x1;
#pragma unroll
            for (int o = 16; o > 0; o >>= 1) s += __shfl_xor_sync(0xffffffffu, s, o);
            float inv = 1.f / s;
            alpn[lane]      = x0 * inv;
            alpn[lane + 32] = x1 * inv;
            __syncwarp();
        }

        // Phase C: gates = sum_p alpn[p]*pre[p] + htpre(+biasM); dual accs;
        // uniform early exit at plen (alpn is exactly 0 beyond plen)
        if (tid < 450) {
            float2 acc0 = bf2f2(prh);
            float2 acc1 = make_float2(0.f, 0.f);
            const float4* al4 = reinterpret_cast<const float4*>(alpn);
#pragma unroll
            for (int q = 0; q < 16; ++q) {
                if (4 * q >= plen) break;
                const float4 av = al4[q];
                float2 w;
                w = bf2f2(pre[4 * q + 0]);
                acc0.x = fmaf(av.x, w.x, acc0.x); acc0.y = fmaf(av.x, w.y, acc0.y);
                w = bf2f2(pre[4 * q + 1]);
                acc1.x = fmaf(av.y, w.x, acc1.x); acc1.y = fmaf(av.y, w.y, acc1.y);
                w = bf2f2(pre[4 * q + 2]);
                acc0.x = fmaf(av.z, w.x, acc0.x); acc0.y = fmaf(av.z, w.y, acc0.y);
                w = bf2f2(pre[4 * q + 3]);
                acc1.x = fmaf(av.w, w.x, acc1.x); acc1.y = fmaf(av.w, w.y, acc1.y);
            }
            scr[2 * tid]     = acc0.x + acc1.x;
            scr[2 * tid + 1] = acc0.y + acc1.y;
        }
        __syncthreads();

        // Phase D: h_m update (MUFU approx)
        if (tid < 300) {
            float gi = scr[tid];
            float gg = scr[tid + 300];
            float go = scr[tid + 600];
            float c  = sig_apx(gi) * tanh_apx(gg);
            hm[tid]  = sig_apx(go) * tanh_apx(c);
        }
        __syncthreads();
    }

    // after the loop hm == h_m[hlen-1]
    if (warp < 3) {
        float acc = 0.f;
        for (int h = lane; h < 300; h += 32) acc += hm[h] * fcw[warp * 300 + h];
#pragma unroll
        for (int o = 16; o > 0; o >>= 1) acc += __shfl_xor_sync(0xffffffffu, acc, o);
        if (lane == 0) red[warp] = acc + fcb[warp];
    }
    __syncthreads();
    if (tid == 0) {
        float l0 = red[0], l1 = red[1], l2 = red[2];
        float mx = fmaxf(l0, fmaxf(l1, l2));
        float e0 = expf(l0 - mx), e1 = expf(l1 - mx), e2 = expf(l2 - mx);
        float inv = 1.f / (e0 + e1 + e2);
        out[b * 3 + 0] = e0 * inv;
        out[b * 3 + 1] = e1 * inv;
        out[b * 3 + 2] = e2 * inv;
    }
}

// ---------------------------------------------------------------------------
extern "C" void kernel_launch(void* const* d_in, const int* in_sizes, int n_in,
                              void* d_out, int out_size)
{
    const int*   premise = (const int*)  d_in[0];
    const int*   plen    = (const int*)  d_in[1];
    const int*   hyp     = (const int*)  d_in[2];
    const int*   hlen    = (const int*)  d_in[3];
    const float* embed   = (const float*)d_in[4];
    const float* w_e     = (const float*)d_in[5];
    const float* W_s     = (const float*)d_in[6];
    const float* W_t     = (const float*)d_in[7];
    const float* W_m     = (const float*)d_in[8];
    const float* fc_w    = (const float*)d_in[9];
    const float* fc_b    = (const float*)d_in[10];
    const float* Wih_p   = (const float*)d_in[11];
    const float* bih_p   = (const float*)d_in[13];
    const float* bhh_p   = (const float*)d_in[14];
    const float* Wih_h   = (const float*)d_in[15];
    const float* bih_h   = (const float*)d_in[17];
    const float* bhh_h   = (const float*)d_in[18];
    const float* Wih_m   = (const float*)d_in[19];
    const float* bih_m   = (const float*)d_in[21];
    const float* bhh_m   = (const float*)d_in[22];

    float* buf = nullptr;
    cudaGetSymbolAddress((void**)&buf, g_buf);
    __nv_bfloat16*  gates1 = (__nv_bfloat16*)(buf + OFF_GATES1);
    __nv_bfloat16*  gates2 = (__nv_bfloat16*)(buf + OFF_GATES2);
    __nv_bfloat16*  hs     = (__nv_bfloat16*)(buf + OFF_HS);
    __nv_bfloat16*  ht     = (__nv_bfloat16*)(buf + OFF_HT);
    __nv_bfloat16*  sprojp = (__nv_bfloat16*)(buf + OFF_SPROJ);
    __nv_bfloat16*  tprojp = (__nv_bfloat16*)(buf + OFF_TPROJ);
    __nv_bfloat16*  htprep = (__nv_bfloat16*)(buf + OFF_HTPRE);
    __nv_bfloat16*  hsWap  = (__nv_bfloat16*)(buf + OFF_HSWA);
    __nv_bfloat16*  embP   = (__nv_bfloat16*)(buf + OFF_EMBP);
    __nv_bfloat16*  embH   = (__nv_bfloat16*)(buf + OFF_EMBH);
    __nv_bfloat16*  Wp     = (__nv_bfloat16*)(buf + OFF_WPB);
    __nv_bfloat16*  Wh     = (__nv_bfloat16*)(buf + OFF_WHB);
    __nv_bfloat16*  Wa     = (__nv_bfloat16*)(buf + OFF_WAB);
    __nv_bfloat16*  Whm    = (__nv_bfloat16*)(buf + OFF_WHMB);
    __nv_bfloat16*  Wsb    = (__nv_bfloat16*)(buf + OFF_WSB);
    __nv_bfloat16*  Wtb    = (__nv_bfloat16*)(buf + OFF_WTB);
    __nv_bfloat16*  WmT    = (__nv_bfloat16*)(buf + OFF_WMTB);
    float* bp = buf + OFF_BP;
    float* bh = buf + OFF_BH;
    float* bm = buf + OFF_BM;

    prep_all<<<(1350000 + 255) / 256, 256>>>(Wih_p, bih_p, bhh_p,
                                             Wih_h, bih_h, bhh_h,
                                             Wih_m, bih_m, bhh_m,
                                             W_m, W_s, W_t,
                                             Wp, Wh, Wa, Whm, Wsb, Wtb, WmT,
                                             bp, bh, bm);

    gather_embed<<<(2 * 8192 * 150 + 255) / 256, 256>>>(embed, premise, hyp,
                                                        embP, embH);

    // encoders via the bf16-A GEMM path (fused bias)
    Pre4 pe;
    pe.A[0] = embP; pe.B[0] = Wp; pe.C[0] = gates1; pe.bias[0] = bp; pe.N[0] = 900;
    pe.A[1] = embH; pe.B[1] = Wh; pe.C[1] = gates2; pe.bias[1] = bh; pe.N[1] = 900;
    pe.A[2] = nullptr; pe.B[2] = nullptr; pe.C[2] = nullptr; pe.bias[2] = nullptr; pe.N[2] = 0;
    pe.A[3] = nullptr; pe.B[3] = nullptr; pe.C[3] = nullptr; pe.bias[3] = nullptr; pe.N[3] = 0;
    gemm_pre<<<dim3(8, 64, 2), 256>>>(pe);

    lstm_act2<<<dim3((8192 * 150 + 255) / 256, 2), 256>>>(gates1, gates2, hs, ht);

    Pre4 pa;
    pa.A[0] = hs;  pa.B[0] = Wa;  pa.C[0] = hsWap;  pa.bias[0] = nullptr; pa.N[0] = 900;
    pa.A[1] = ht;  pa.B[1] = Whm; pa.C[1] = htprep; pa.bias[1] = bm;      pa.N[1] = 900;
    pa.A[2] = hs;  pa.B[2] = Wsb; pa.C[2] = sprojp; pa.bias[2] = nullptr; pa.N[2] = 300;
    pa.A[3] = ht;  pa.B[3] = Wtb; pa.C[3] = tprojp; pa.bias[3] = nullptr; pa.N[3] = 300;
    gemm_pre<<<dim3(8, 64, 4), 256>>>(pa);

    cudaFuncSetAttribute(scan_kernel, cudaFuncAttributeMaxDynamicSharedMemorySize,
                         SCAN_SMEM_BYTES);
    scan_kernel<<<128, 512, SCAN_SMEM_BYTES>>>(sprojp, tprojp, htprep, hsWap, WmT,
                                               w_e, plen, hlen, fc_w, fc_b,
                                               (float*)d_out);
}